// round 3
// baseline (speedup 1.0000x reference)
#include <cuda_runtime.h>
#include <cstddef>

#define MAX_N      100000
#define K_NEIGH    16
#define DIM_IN     128
#define DIM_H      256
#define DIM_OUT    128
#define EPS_BN     1e-5f
#define SLOPE      0.2f

#define BM 128
#define BN 64
#define BK 16
#define TM 8
#define TN 4
#define MAX_TILES  ((MAX_N + BM - 1) / BM)   // 782

static inline int cdiv(int a, int b) { return (a + b - 1) / b; }

// ---------------- scratch (static device allocations; no cudaMalloc) --------
__device__ float g_y1[(size_t)MAX_N * DIM_H];     // LReLU(X W1^T + b1), pre-BN
__device__ float g_y2[(size_t)MAX_N * DIM_H];     // LReLU(f1 W2^T + b2), pre-BN
__device__ float g_y3[(size_t)MAX_N * DIM_OUT];   // LReLU(f2 W3^T + b3), pre-BN
__device__ float g_psum[(size_t)MAX_TILES * DIM_H];
__device__ float g_psq [(size_t)MAX_TILES * DIM_H];
__device__ float g_sa1[DIM_H], g_sb1[DIM_H];
__device__ float g_sa2[DIM_H], g_sb2[DIM_H];
__device__ float g_sa3[DIM_OUT], g_sb3[DIM_OUT];

// ---------------------------------------------------------------------------
// Fused GEMM: C = LReLU( norm(A) @ W^T + bias ), with per-(rowtile, col)
// partial sum / sumsq written deterministically for the following BatchNorm.
//   A: [Nrows, HIN] row-major (raw pre-BN activations of previous layer)
//   norm(x)[.,c] = x*sa[c] + sb[c]   (identity when NORM=false)
//   W: [HOUT, HIN] row-major
// Tiling: 128x64 block tile, BK=16, 256 threads, 8x4 per thread, register
// prefetch double-buffering on the global->smem path.
// ---------------------------------------------------------------------------
template<int HIN, int HOUT, bool NORM>
__global__ __launch_bounds__(256)
void gemm_fused(const float* __restrict__ A,
                const float* __restrict__ W,
                const float* __restrict__ bias,
                const float* __restrict__ sa,
                const float* __restrict__ sb,
                float* __restrict__ C,
                float* __restrict__ psum,
                float* __restrict__ psq,
                int Nrows)
{
    constexpr int KT = HIN / BK;

    __shared__ float As[BK][BM];
    __shared__ float Ws[BK][BN];
    __shared__ float s_sa[NORM ? HIN : 1];
    __shared__ float s_sb[NORM ? HIN : 1];

    const int tid = threadIdx.x;
    const int tx  = tid & 15;    // 16 column groups * TN=4 -> 64 cols
    const int ty  = tid >> 4;    // 16 row groups    * TM=8 -> 128 rows
    const int r0  = blockIdx.x * BM;
    const int c0  = blockIdx.y * BN;

    if (NORM) {
        for (int i = tid; i < HIN; i += 256) { s_sa[i] = sa[i]; s_sb[i] = sb[i]; }
        __syncthreads();
    }

    // global-load assignments
    const int aRow0 = tid >> 2;          // rows 0..63
    const int aRow1 = aRow0 + 64;        // rows 64..127
    const int aK    = (tid & 3) << 2;    // k offset within BK (float4)
    const int wRow  = tid >> 2;          // 0..63 output column
    const int wK    = (tid & 3) << 2;

    const int gr0 = r0 + aRow0;
    const int gr1 = r0 + aRow1;
    const bool vld0 = gr0 < Nrows;
    const bool vld1 = gr1 < Nrows;
    const float* Ap0 = A + (size_t)gr0 * HIN + aK;
    const float* Ap1 = A + (size_t)gr1 * HIN + aK;
    const float* Wp  = W + (size_t)(c0 + wRow) * HIN + wK;

    const float4 z4 = make_float4(0.f, 0.f, 0.f, 0.f);
    float4 pa0 = vld0 ? *(const float4*)Ap0 : z4;
    float4 pa1 = vld1 ? *(const float4*)Ap1 : z4;
    float4 pw  = *(const float4*)Wp;

    float acc[TM][TN];
    #pragma unroll
    for (int i = 0; i < TM; ++i)
        #pragma unroll
        for (int j = 0; j < TN; ++j) acc[i][j] = 0.f;

    #pragma unroll 1
    for (int kt = 0; kt < KT; ++kt) {
        // ---- store prefetched tile to smem (apply BN affine on the fly) ----
        {
            float4 q0 = pa0, q1 = pa1;
            if (NORM) {
                const int kk = kt * BK + aK;
                q0.x = fmaf(q0.x, s_sa[kk + 0], s_sb[kk + 0]);
                q0.y = fmaf(q0.y, s_sa[kk + 1], s_sb[kk + 1]);
                q0.z = fmaf(q0.z, s_sa[kk + 2], s_sb[kk + 2]);
                q0.w = fmaf(q0.w, s_sa[kk + 3], s_sb[kk + 3]);
                q1.x = fmaf(q1.x, s_sa[kk + 0], s_sb[kk + 0]);
                q1.y = fmaf(q1.y, s_sa[kk + 1], s_sb[kk + 1]);
                q1.z = fmaf(q1.z, s_sa[kk + 2], s_sb[kk + 2]);
                q1.w = fmaf(q1.w, s_sa[kk + 3], s_sb[kk + 3]);
            }
            As[aK + 0][aRow0] = q0.x;  As[aK + 1][aRow0] = q0.y;
            As[aK + 2][aRow0] = q0.z;  As[aK + 3][aRow0] = q0.w;
            As[aK + 0][aRow1] = q1.x;  As[aK + 1][aRow1] = q1.y;
            As[aK + 2][aRow1] = q1.z;  As[aK + 3][aRow1] = q1.w;
            Ws[wK + 0][wRow]  = pw.x;  Ws[wK + 1][wRow]  = pw.y;
            Ws[wK + 2][wRow]  = pw.z;  Ws[wK + 3][wRow]  = pw.w;
        }
        __syncthreads();

        // ---- prefetch next tile into registers (overlaps with compute) ----
        if (kt + 1 < KT) {
            const int off = (kt + 1) * BK;
            pa0 = vld0 ? *(const float4*)(Ap0 + off) : z4;
            pa1 = vld1 ? *(const float4*)(Ap1 + off) : z4;
            pw  = *(const float4*)(Wp + off);
        }

        // ---- compute ----
        #pragma unroll
        for (int k = 0; k < BK; ++k) {
            float4 a0 = *(const float4*)&As[k][ty * TM];
            float4 a1 = *(const float4*)&As[k][ty * TM + 4];
            float4 b  = *(const float4*)&Ws[k][tx * TN];
            float ra[TM] = {a0.x, a0.y, a0.z, a0.w, a1.x, a1.y, a1.z, a1.w};
            float rb[TN] = {b.x, b.y, b.z, b.w};
            #pragma unroll
            for (int i = 0; i < TM; ++i)
                #pragma unroll
                for (int j = 0; j < TN; ++j)
                    acc[i][j] = fmaf(ra[i], rb[j], acc[i][j]);
        }
        __syncthreads();
    }

    // ---- epilogue: bias + LeakyReLU + store + per-block column stats ----
    const int gcol = c0 + tx * TN;
    float bj[TN];
    #pragma unroll
    for (int j = 0; j < TN; ++j) bj[j] = __ldg(&bias[gcol + j]);

    float csum[TN] = {0.f, 0.f, 0.f, 0.f};
    float csq [TN] = {0.f, 0.f, 0.f, 0.f};

    #pragma unroll
    for (int i = 0; i < TM; ++i) {
        const int grow = r0 + ty * TM + i;
        float t[TN];
        #pragma unroll
        for (int j = 0; j < TN; ++j) {
            float c = acc[i][j] + bj[j];
            t[j] = (c > 0.f) ? c : SLOPE * c;
        }
        if (grow < Nrows) {
            *(float4*)&C[(size_t)grow * HOUT + gcol] =
                make_float4(t[0], t[1], t[2], t[3]);
            #pragma unroll
            for (int j = 0; j < TN; ++j) {
                csum[j] += t[j];
                csq[j]  = fmaf(t[j], t[j], csq[j]);
            }
        }
    }

    // deterministic intra-block reduction (reuse Ws as [16][64] buffer)
    float* red = &Ws[0][0];
    #pragma unroll
    for (int j = 0; j < TN; ++j) red[ty * BN + tx * TN + j] = csum[j];
    __syncthreads();
    if (tid < BN) {
        float s = 0.f;
        #pragma unroll
        for (int t2 = 0; t2 < 16; ++t2) s += red[t2 * BN + tid];
        psum[(size_t)blockIdx.x * HOUT + c0 + tid] = s;
    }
    __syncthreads();
    #pragma unroll
    for (int j = 0; j < TN; ++j) red[ty * BN + tx * TN + j] = csq[j];
    __syncthreads();
    if (tid < BN) {
        float s = 0.f;
        #pragma unroll
        for (int t2 = 0; t2 < 16; ++t2) s += red[t2 * BN + tid];
        psq[(size_t)blockIdx.x * HOUT + c0 + tid] = s;
    }
}

// ---------------------------------------------------------------------------
// Reduce tile partials -> per-channel BN affine (sa = rstd*gamma,
// sb = beta - mean*sa). Deterministic serial reduction over tiles.
// ---------------------------------------------------------------------------
__global__ void finalize_stats(const float* __restrict__ psum,
                               const float* __restrict__ psq,
                               const float* __restrict__ gamma,
                               const float* __restrict__ beta,
                               float* __restrict__ sa,
                               float* __restrict__ sb,
                               int H, int ntiles, float invN)
{
    const int c = blockIdx.x * blockDim.x + threadIdx.x;
    if (c >= H) return;
    float s1 = 0.f, s2 = 0.f;
    for (int t = 0; t < ntiles; ++t) {
        s1 += psum[(size_t)t * H + c];
        s2 += psq [(size_t)t * H + c];
    }
    const float m   = s1 * invN;
    const float var = fmaf(-m, m, s2 * invN);
    const float r   = rsqrtf(var + EPS_BN);
    const float a   = r * gamma[c];
    sa[c] = a;
    sb[c] = fmaf(-m, a, beta[c]);
}

// ---------------------------------------------------------------------------
// f = y3 * sa3[col] + sb3[col]   (final BN), float4 vectorized
// ---------------------------------------------------------------------------
__global__ void norm_f_kernel(const float* __restrict__ y,
                              const float* __restrict__ sa,
                              const float* __restrict__ sb,
                              float* __restrict__ f,
                              int total4)   // N * DIM_OUT / 4
{
    const int i = blockIdx.x * blockDim.x + threadIdx.x;
    if (i >= total4) return;
    float4 v = ((const float4*)y)[i];
    const int col = (i & (DIM_OUT / 4 - 1)) * 4;
    v.x = fmaf(v.x, __ldg(&sa[col + 0]), __ldg(&sb[col + 0]));
    v.y = fmaf(v.y, __ldg(&sa[col + 1]), __ldg(&sb[col + 1]));
    v.z = fmaf(v.z, __ldg(&sa[col + 2]), __ldg(&sb[col + 2]));
    v.w = fmaf(v.w, __ldg(&sa[col + 3]), __ldg(&sb[col + 3]));
    ((float4*)f)[i] = v;
}

// ---------------------------------------------------------------------------
// node_update[i] = mean_k f[neigh_idx[i*K+k]]
// one warp per node; lane handles 4 contiguous floats (float4 coalesced rows).
// f is 51.2MB -> mostly L2-resident.
// ---------------------------------------------------------------------------
__global__ void gather_mean_kernel(const float* __restrict__ f,
                                   const int* __restrict__ idx,
                                   float* __restrict__ out,
                                   int Nn)
{
    const int node = blockIdx.x * (blockDim.x >> 5) + (threadIdx.x >> 5);
    const int lane = threadIdx.x & 31;
    if (node >= Nn) return;
    const int* ip = idx + (size_t)node * K_NEIGH;
    float4 s = make_float4(0.f, 0.f, 0.f, 0.f);
    #pragma unroll
    for (int k = 0; k < K_NEIGH; ++k) {
        const int id = __ldg(&ip[k]);
        const float4 v = *(const float4*)&f[(size_t)id * DIM_OUT + lane * 4];
        s.x += v.x; s.y += v.y; s.z += v.z; s.w += v.w;
    }
    const float inv = 1.f / K_NEIGH;
    s.x *= inv; s.y *= inv; s.z *= inv; s.w *= inv;
    *(float4*)&out[(size_t)node * DIM_OUT + lane * 4] = s;
}

// ---------------------------------------------------------------------------
extern "C" void kernel_launch(void* const* d_in, const int* in_sizes, int n_in,
                              void* d_out, int out_size)
{
    const float* X    = (const float*)d_in[0];
    const int*   nidx = (const int*)  d_in[1];
    // d_in[2] = prob_retained (unused)
    const float* W1 = (const float*)d_in[3];
    const float* b1 = (const float*)d_in[4];
    const float* g1 = (const float*)d_in[5];
    const float* e1 = (const float*)d_in[6];
    const float* W2 = (const float*)d_in[7];
    const float* b2 = (const float*)d_in[8];
    const float* g2 = (const float*)d_in[9];
    const float* e2 = (const float*)d_in[10];
    const float* W3 = (const float*)d_in[11];
    const float* b3 = (const float*)d_in[12];
    const float* g3 = (const float*)d_in[13];
    const float* e3 = (const float*)d_in[14];

    const int N = in_sizes[0] / DIM_IN;     // 100000
    const int ntiles = cdiv(N, BM);         // 782
    const float invN = 1.f / (float)N;

    float *y1, *y2, *y3, *ps, *pq, *sa1, *sb1, *sa2, *sb2, *sa3, *sb3;
    cudaGetSymbolAddress((void**)&y1,  g_y1);
    cudaGetSymbolAddress((void**)&y2,  g_y2);
    cudaGetSymbolAddress((void**)&y3,  g_y3);
    cudaGetSymbolAddress((void**)&ps,  g_psum);
    cudaGetSymbolAddress((void**)&pq,  g_psq);
    cudaGetSymbolAddress((void**)&sa1, g_sa1);
    cudaGetSymbolAddress((void**)&sb1, g_sb1);
    cudaGetSymbolAddress((void**)&sa2, g_sa2);
    cudaGetSymbolAddress((void**)&sb2, g_sb2);
    cudaGetSymbolAddress((void**)&sa3, g_sa3);
    cudaGetSymbolAddress((void**)&sb3, g_sb3);

    float* out         = (float*)d_out;
    float* node_update = out;                       // [N, DIM_OUT]
    float* fbuf        = out + (size_t)N * DIM_OUT; // [N, DIM_OUT]

    // Layer 1: y1 = LReLU(X W1^T + b1), stats
    gemm_fused<DIM_IN, DIM_H, false><<<dim3(ntiles, DIM_H / BN), 256>>>(
        X, W1, b1, nullptr, nullptr, y1, ps, pq, N);
    finalize_stats<<<cdiv(DIM_H, 128), 128>>>(ps, pq, g1, e1, sa1, sb1,
                                              DIM_H, ntiles, invN);
    // Layer 2: y2 = LReLU(BN1(y1) W2^T + b2), stats
    gemm_fused<DIM_H, DIM_H, true><<<dim3(ntiles, DIM_H / BN), 256>>>(
        y1, W2, b2, sa1, sb1, y2, ps, pq, N);
    finalize_stats<<<cdiv(DIM_H, 128), 128>>>(ps, pq, g2, e2, sa2, sb2,
                                              DIM_H, ntiles, invN);
    // Layer 3: y3 = LReLU(BN2(y2) W3^T + b3), stats
    gemm_fused<DIM_H, DIM_OUT, true><<<dim3(ntiles, DIM_OUT / BN), 256>>>(
        y2, W3, b3, sa2, sb2, y3, ps, pq, N);
    finalize_stats<<<cdiv(DIM_OUT, 128), 128>>>(ps, pq, g3, e3, sa3, sb3,
                                               DIM_OUT, ntiles, invN);
    // f = BN3(y3) -> second half of output
    const int total4 = N * DIM_OUT / 4;
    norm_f_kernel<<<cdiv(total4, 256), 256>>>(y3, sa3, sb3, fbuf, total4);
    // node_update = neighbor mean of f -> first half of output
    gather_mean_kernel<<<cdiv(N, 8), 256>>>(fbuf, nidx, node_update, N);
}

// round 8
// speedup vs baseline: 1.4063x; 1.4063x over previous
#include <cuda_runtime.h>
#include <cstddef>

#define MAX_N      100000
#define K_NEIGH    16
#define DIM_IN     128
#define DIM_H      256
#define DIM_OUT    128
#define EPS_BN     1e-5f
#define SLOPE      0.2f

#define BM 128
#define BN 64
#define BK 16
#define TM 8
#define TN 4
#define MAX_TILES  ((MAX_N + BM - 1) / BM)   // 782

static inline int cdiv(int a, int b) { return (a + b - 1) / b; }

// ---------------- scratch (static device allocations; no cudaMalloc) --------
__device__ float g_y1[(size_t)MAX_N * DIM_H];
__device__ float g_y2[(size_t)MAX_N * DIM_H];
__device__ float g_y3[(size_t)MAX_N * DIM_OUT];
__device__ float g_psum[(size_t)DIM_H * MAX_TILES];   // [channel][tile] layout
__device__ float g_psq [(size_t)DIM_H * MAX_TILES];
__device__ float g_sa1[DIM_H], g_sb1[DIM_H];
__device__ float g_sa2[DIM_H], g_sb2[DIM_H];
__device__ float g_sa3[DIM_OUT], g_sb3[DIM_OUT];

// ---------------- packed f32x2 helpers (sm_100+ PTX) ------------------------
__device__ __forceinline__ unsigned long long pack2_bcast(float x) {
    unsigned long long r;
    asm("mov.b64 %0, {%1, %1};" : "=l"(r) : "f"(x));
    return r;
}
__device__ __forceinline__ void fma2(unsigned long long& d,
                                     unsigned long long a,
                                     unsigned long long b) {
    asm("fma.rn.f32x2 %0, %1, %2, %0;" : "+l"(d) : "l"(a), "l"(b));
}
__device__ __forceinline__ void unpack2(unsigned long long v, float& lo, float& hi) {
    asm("mov.b64 {%0, %1}, %2;" : "=f"(lo), "=f"(hi) : "l"(v));
}

// ---------------------------------------------------------------------------
// Fused GEMM: C = LReLU( norm(A) @ W^T + bias ) + per-(rowtile,col) partial
// sum/sumsq for the following BatchNorm. Inner product uses packed
// fma.rn.f32x2 (FFMA2): accumulator pairs along M so the A operand arrives
// pre-packed from LDS.64; only B-broadcasts need mov.b64 packing.
// ---------------------------------------------------------------------------
template<int HIN, int HOUT, bool NORM>
__global__ __launch_bounds__(256)
void gemm_fused(const float* __restrict__ A,
                const float* __restrict__ W,
                const float* __restrict__ bias,
                const float* __restrict__ sa,
                const float* __restrict__ sb,
                float* __restrict__ C,
                float* __restrict__ psum,
                float* __restrict__ psq,
                int Nrows)
{
    constexpr int KT = HIN / BK;

    __shared__ __align__(16) float As[BK][BM];
    __shared__ __align__(16) float Ws[BK][BN];
    __shared__ float s_sa[NORM ? HIN : 1];
    __shared__ float s_sb[NORM ? HIN : 1];

    const int tid = threadIdx.x;
    const int tx  = tid & 15;    // 16 col groups * TN=4 -> 64 cols
    const int ty  = tid >> 4;    // 16 row groups * TM=8 -> 128 rows
    const int r0  = blockIdx.x * BM;
    const int c0  = blockIdx.y * BN;

    if (NORM) {
        for (int i = tid; i < HIN; i += 256) { s_sa[i] = sa[i]; s_sb[i] = sb[i]; }
        __syncthreads();
    }

    const int aRow0 = tid >> 2;          // rows 0..63
    const int aRow1 = aRow0 + 64;        // rows 64..127
    const int aK    = (tid & 3) << 2;    // k offset within BK (float4)
    const int wRow  = tid >> 2;
    const int wK    = (tid & 3) << 2;

    const int gr0 = r0 + aRow0;
    const int gr1 = r0 + aRow1;
    const bool vld0 = gr0 < Nrows;
    const bool vld1 = gr1 < Nrows;
    const float* Ap0 = A + (size_t)gr0 * HIN + aK;
    const float* Ap1 = A + (size_t)gr1 * HIN + aK;
    const float* Wp  = W + (size_t)(c0 + wRow) * HIN + wK;

    const float4 z4 = make_float4(0.f, 0.f, 0.f, 0.f);
    float4 pa0 = vld0 ? *(const float4*)Ap0 : z4;
    float4 pa1 = vld1 ? *(const float4*)Ap1 : z4;
    float4 pw  = *(const float4*)Wp;

    // acc2[i2][j] = packed pair (row 2*i2, row 2*i2+1) x col j
    unsigned long long acc2[TM / 2][TN];
    #pragma unroll
    for (int i = 0; i < TM / 2; ++i)
        #pragma unroll
        for (int j = 0; j < TN; ++j) acc2[i][j] = 0ull;

    #pragma unroll 1
    for (int kt = 0; kt < KT; ++kt) {
        {
            float4 q0 = pa0, q1 = pa1;
            if (NORM) {
                const int kk = kt * BK + aK;
                q0.x = fmaf(q0.x, s_sa[kk + 0], s_sb[kk + 0]);
                q0.y = fmaf(q0.y, s_sa[kk + 1], s_sb[kk + 1]);
                q0.z = fmaf(q0.z, s_sa[kk + 2], s_sb[kk + 2]);
                q0.w = fmaf(q0.w, s_sa[kk + 3], s_sb[kk + 3]);
                q1.x = fmaf(q1.x, s_sa[kk + 0], s_sb[kk + 0]);
                q1.y = fmaf(q1.y, s_sa[kk + 1], s_sb[kk + 1]);
                q1.z = fmaf(q1.z, s_sa[kk + 2], s_sb[kk + 2]);
                q1.w = fmaf(q1.w, s_sa[kk + 3], s_sb[kk + 3]);
            }
            As[aK + 0][aRow0] = q0.x;  As[aK + 1][aRow0] = q0.y;
            As[aK + 2][aRow0] = q0.z;  As[aK + 3][aRow0] = q0.w;
            As[aK + 0][aRow1] = q1.x;  As[aK + 1][aRow1] = q1.y;
            As[aK + 2][aRow1] = q1.z;  As[aK + 3][aRow1] = q1.w;
            Ws[wK + 0][wRow]  = pw.x;  Ws[wK + 1][wRow]  = pw.y;
            Ws[wK + 2][wRow]  = pw.z;  Ws[wK + 3][wRow]  = pw.w;
        }
        __syncthreads();

        if (kt + 1 < KT) {
            const int off = (kt + 1) * BK;
            pa0 = vld0 ? *(const float4*)(Ap0 + off) : z4;
            pa1 = vld1 ? *(const float4*)(Ap1 + off) : z4;
            pw  = *(const float4*)(Wp + off);
        }

        #pragma unroll
        for (int k = 0; k < BK; ++k) {
            // A rows arrive pre-packed: 4 x LDS.64 (consecutive row pairs)
            const unsigned long long* a2p =
                (const unsigned long long*)&As[k][ty * TM];
            unsigned long long ra2[TM / 2];
            #pragma unroll
            for (int i = 0; i < TM / 2; ++i) ra2[i] = a2p[i];

            float4 b = *(const float4*)&Ws[k][tx * TN];
            unsigned long long rb2[TN] = {
                pack2_bcast(b.x), pack2_bcast(b.y),
                pack2_bcast(b.z), pack2_bcast(b.w)
            };

            #pragma unroll
            for (int i = 0; i < TM / 2; ++i)
                #pragma unroll
                for (int j = 0; j < TN; ++j)
                    fma2(acc2[i][j], ra2[i], rb2[j]);
        }
        __syncthreads();
    }

    // ---- epilogue: bias + LeakyReLU + store + per-block column stats ----
    const int gcol = c0 + tx * TN;
    float bj[TN];
    #pragma unroll
    for (int j = 0; j < TN; ++j) bj[j] = __ldg(&bias[gcol + j]);

    float csum[TN] = {0.f, 0.f, 0.f, 0.f};
    float csq [TN] = {0.f, 0.f, 0.f, 0.f};

    #pragma unroll
    for (int i2 = 0; i2 < TM / 2; ++i2) {
        float v0[TN], v1[TN];
        #pragma unroll
        for (int j = 0; j < TN; ++j) unpack2(acc2[i2][j], v0[j], v1[j]);

        #pragma unroll
        for (int h = 0; h < 2; ++h) {
            const int grow = r0 + ty * TM + 2 * i2 + h;
            float* src = h ? v1 : v0;
            float t[TN];
            #pragma unroll
            for (int j = 0; j < TN; ++j) {
                float c = src[j] + bj[j];
                t[j] = (c > 0.f) ? c : SLOPE * c;
            }
            if (grow < Nrows) {
                *(float4*)&C[(size_t)grow * HOUT + gcol] =
                    make_float4(t[0], t[1], t[2], t[3]);
                #pragma unroll
                for (int j = 0; j < TN; ++j) {
                    csum[j] += t[j];
                    csq[j]  = fmaf(t[j], t[j], csq[j]);
                }
            }
        }
    }

    // deterministic intra-block reduction (reuse Ws as [16][64] buffer)
    // partials stored TRANSPOSED: psum[channel * ntiles + tile]
    const int ntiles = gridDim.x;
    float* red = &Ws[0][0];
    #pragma unroll
    for (int j = 0; j < TN; ++j) red[ty * BN + tx * TN + j] = csum[j];
    __syncthreads();
    if (tid < BN) {
        float s = 0.f;
        #pragma unroll
        for (int t2 = 0; t2 < 16; ++t2) s += red[t2 * BN + tid];
        psum[(size_t)(c0 + tid) * ntiles + blockIdx.x] = s;
    }
    __syncthreads();
    #pragma unroll
    for (int j = 0; j < TN; ++j) red[ty * BN + tx * TN + j] = csq[j];
    __syncthreads();
    if (tid < BN) {
        float s = 0.f;
        #pragma unroll
        for (int t2 = 0; t2 < 16; ++t2) s += red[t2 * BN + tid];
        psq[(size_t)(c0 + tid) * ntiles + blockIdx.x] = s;
    }
}

// ---------------------------------------------------------------------------
// Parallel, deterministic stats finalize: one block per channel, coalesced
// strided loads over the [channel][tile] partials, fixed-order tree reduce.
// ---------------------------------------------------------------------------
__global__ __launch_bounds__(128)
void finalize_stats(const float* __restrict__ psum,
                    const float* __restrict__ psq,
                    const float* __restrict__ gamma,
                    const float* __restrict__ beta,
                    float* __restrict__ sa,
                    float* __restrict__ sb,
                    int ntiles, float invN)
{
    const int c   = blockIdx.x;
    const int tid = threadIdx.x;
    const float* p1 = psum + (size_t)c * ntiles;
    const float* p2 = psq  + (size_t)c * ntiles;

    float s1 = 0.f, s2 = 0.f;
    for (int t = tid; t < ntiles; t += 128) {
        s1 += p1[t];
        s2 += p2[t];
    }

    __shared__ float r1[128], r2[128];
    r1[tid] = s1; r2[tid] = s2;
    __syncthreads();
    #pragma unroll
    for (int s = 64; s > 0; s >>= 1) {
        if (tid < s) { r1[tid] += r1[tid + s]; r2[tid] += r2[tid + s]; }
        __syncthreads();
    }

    if (tid == 0) {
        const float m   = r1[0] * invN;
        const float var = fmaf(-m, m, r2[0] * invN);
        const float r   = rsqrtf(var + EPS_BN);
        const float a   = r * gamma[c];
        sa[c] = a;
        sb[c] = fmaf(-m, a, beta[c]);
    }
}

// ---------------------------------------------------------------------------
// f = y3 * sa3[col] + sb3[col]   (final BN), float4 vectorized
// ---------------------------------------------------------------------------
__global__ void norm_f_kernel(const float* __restrict__ y,
                              const float* __restrict__ sa,
                              const float* __restrict__ sb,
                              float* __restrict__ f,
                              int total4)
{
    const int i = blockIdx.x * blockDim.x + threadIdx.x;
    if (i >= total4) return;
    float4 v = ((const float4*)y)[i];
    const int col = (i & (DIM_OUT / 4 - 1)) * 4;
    v.x = fmaf(v.x, __ldg(&sa[col + 0]), __ldg(&sb[col + 0]));
    v.y = fmaf(v.y, __ldg(&sa[col + 1]), __ldg(&sb[col + 1]));
    v.z = fmaf(v.z, __ldg(&sa[col + 2]), __ldg(&sb[col + 2]));
    v.w = fmaf(v.w, __ldg(&sa[col + 3]), __ldg(&sb[col + 3]));
    ((float4*)f)[i] = v;
}

// ---------------------------------------------------------------------------
// node_update[i] = mean_k f[neigh_idx[i*K+k]] ; one warp per node.
// ---------------------------------------------------------------------------
__global__ void gather_mean_kernel(const float* __restrict__ f,
                                   const int* __restrict__ idx,
                                   float* __restrict__ out,
                                   int Nn)
{
    const int node = blockIdx.x * (blockDim.x >> 5) + (threadIdx.x >> 5);
    const int lane = threadIdx.x & 31;
    if (node >= Nn) return;
    const int* ip = idx + (size_t)node * K_NEIGH;
    float4 s = make_float4(0.f, 0.f, 0.f, 0.f);
    #pragma unroll
    for (int k = 0; k < K_NEIGH; ++k) {
        const int id = __ldg(&ip[k]);
        const float4 v = *(const float4*)&f[(size_t)id * DIM_OUT + lane * 4];
        s.x += v.x; s.y += v.y; s.z += v.z; s.w += v.w;
    }
    const float inv = 1.f / K_NEIGH;
    s.x *= inv; s.y *= inv; s.z *= inv; s.w *= inv;
    *(float4*)&out[(size_t)node * DIM_OUT + lane * 4] = s;
}

// ---------------------------------------------------------------------------
extern "C" void kernel_launch(void* const* d_in, const int* in_sizes, int n_in,
                              void* d_out, int out_size)
{
    const float* X    = (const float*)d_in[0];
    const int*   nidx = (const int*)  d_in[1];
    const float* W1 = (const float*)d_in[3];
    const float* b1 = (const float*)d_in[4];
    const float* g1 = (const float*)d_in[5];
    const float* e1 = (const float*)d_in[6];
    const float* W2 = (const float*)d_in[7];
    const float* b2 = (const float*)d_in[8];
    const float* g2 = (const float*)d_in[9];
    const float* e2 = (const float*)d_in[10];
    const float* W3 = (const float*)d_in[11];
    const float* b3 = (const float*)d_in[12];
    const float* g3 = (const float*)d_in[13];
    const float* e3 = (const float*)d_in[14];

    const int N = in_sizes[0] / DIM_IN;
    const int ntiles = cdiv(N, BM);
    const float invN = 1.f / (float)N;

    float *y1, *y2, *y3, *ps, *pq, *sa1, *sb1, *sa2, *sb2, *sa3, *sb3;
    cudaGetSymbolAddress((void**)&y1,  g_y1);
    cudaGetSymbolAddress((void**)&y2,  g_y2);
    cudaGetSymbolAddress((void**)&y3,  g_y3);
    cudaGetSymbolAddress((void**)&ps,  g_psum);
    cudaGetSymbolAddress((void**)&pq,  g_psq);
    cudaGetSymbolAddress((void**)&sa1, g_sa1);
    cudaGetSymbolAddress((void**)&sb1, g_sb1);
    cudaGetSymbolAddress((void**)&sa2, g_sa2);
    cudaGetSymbolAddress((void**)&sb2, g_sb2);
    cudaGetSymbolAddress((void**)&sa3, g_sa3);
    cudaGetSymbolAddress((void**)&sb3, g_sb3);

    float* out         = (float*)d_out;
    float* node_update = out;
    float* fbuf        = out + (size_t)N * DIM_OUT;

    gemm_fused<DIM_IN, DIM_H, false><<<dim3(ntiles, DIM_H / BN), 256>>>(
        X, W1, b1, nullptr, nullptr, y1, ps, pq, N);
    finalize_stats<<<DIM_H, 128>>>(ps, pq, g1, e1, sa1, sb1, ntiles, invN);

    gemm_fused<DIM_H, DIM_H, true><<<dim3(ntiles, DIM_H / BN), 256>>>(
        y1, W2, b2, sa1, sb1, y2, ps, pq, N);
    finalize_stats<<<DIM_H, 128>>>(ps, pq, g2, e2, sa2, sb2, ntiles, invN);

    gemm_fused<DIM_H, DIM_OUT, true><<<dim3(ntiles, DIM_OUT / BN), 256>>>(
        y2, W3, b3, sa2, sb2, y3, ps, pq, N);
    finalize_stats<<<DIM_OUT, 128>>>(ps, pq, g3, e3, sa3, sb3, ntiles, invN);

    const int total4 = N * DIM_OUT / 4;
    norm_f_kernel<<<cdiv(total4, 256), 256>>>(y3, sa3, sb3, fbuf, total4);
    gather_mean_kernel<<<cdiv(N, 8), 256>>>(fbuf, nidx, node_update, N);
}